// round 2
// baseline (speedup 1.0000x reference)
#include <cuda_runtime.h>
#include <stdint.h>

// out[i, 0:8] = params[idx[i]] * xs[i, 0:8]
// xs: float32 [N, 8]; idx: int32 [N] (JAX default x64-disabled downcasts the
// declared int64 to int32!); params: float32 [V, 1]; out: float32 [N, 8]
// N = 4194304, D = 8, V = 1048576.
//
// HBM-bound: one thread per row, two float4 loads + two float4 stores,
// param gather serviced from L2 (4 MB table << 126 MB L2).

#define N_ROWS 4194304

__global__ __launch_bounds__(256) void gather_mul_kernel(
    const float4* __restrict__ xs,    // [N, 2] as float4
    const int* __restrict__ idx,      // [N] int32
    const float* __restrict__ params, // [V]
    float4* __restrict__ out)         // [N, 2] as float4
{
    int i = blockIdx.x * blockDim.x + threadIdx.x;
    if (i >= N_ROWS) return;

    // Issue all loads up front for MLP.
    int j = idx[i];
    float4 x0 = xs[2 * i];
    float4 x1 = xs[2 * i + 1];
    float p = __ldg(params + j);

    float4 o0, o1;
    o0.x = p * x0.x; o0.y = p * x0.y; o0.z = p * x0.z; o0.w = p * x0.w;
    o1.x = p * x1.x; o1.y = p * x1.y; o1.z = p * x1.z; o1.w = p * x1.w;

    out[2 * i]     = o0;
    out[2 * i + 1] = o1;
}

extern "C" void kernel_launch(void* const* d_in, const int* in_sizes, int n_in,
                              void* d_out, int out_size)
{
    const float4* xs     = (const float4*)d_in[0];
    const int*    idx    = (const int*)d_in[1];
    const float*  params = (const float*)d_in[2];
    float4*       out    = (float4*)d_out;

    const int threads = 256;
    const int blocks = (N_ROWS + threads - 1) / threads;  // 16384
    gather_mul_kernel<<<blocks, threads>>>(xs, idx, params, out);
}

// round 3
// speedup vs baseline: 1.0404x; 1.0404x over previous
#include <cuda_runtime.h>
#include <stdint.h>

// out[i, 0:8] = params[idx[i]] * xs[i, 0:8]
// xs: float32 [N, 8]; idx: int32 [N]; params: float32 [V]; out: float32 [N, 8]
// N = 4194304, V = 1048576.
//
// HBM-bound with an L2-resident random gather. Grid-stride unroll-4:
// front-batched loads give ~16 independent memory ops in flight per thread
// to cover the idx(DRAM) -> param(L2) dependent chain.

#define N_ROWS   4194304
#define UNROLL   4
#define THREADS  256
#define BLOCKS   (N_ROWS / (UNROLL * THREADS))   // 4096

__global__ __launch_bounds__(THREADS) void gather_mul_kernel(
    const float4* __restrict__ xs,    // [N, 2] as float4
    const int*    __restrict__ idx,   // [N] int32
    const float*  __restrict__ params,// [V]
    float4*       __restrict__ out)   // [N, 2] as float4
{
    const int tid    = blockIdx.x * THREADS + threadIdx.x;
    const int stride = BLOCKS * THREADS;   // 1048576 threads total

    // Row k for this thread: tid + k*stride. Every instruction below is
    // fully coalesced across the warp (lane-contiguous addresses).

    // 1) Batch the index loads (DRAM latency exposed first).
    int j[UNROLL];
#pragma unroll
    for (int k = 0; k < UNROLL; k++)
        j[k] = idx[tid + k * stride];

    // 2) Batch the param gathers (L2 hits, random sectors).
    float p[UNROLL];
#pragma unroll
    for (int k = 0; k < UNROLL; k++)
        p[k] = __ldg(params + j[k]);

    // 3) Batch the xs row loads (2 x float4 each).
    float4 x0[UNROLL], x1[UNROLL];
#pragma unroll
    for (int k = 0; k < UNROLL; k++) {
        const int r = tid + k * stride;
        x0[k] = xs[2 * r];
        x1[k] = xs[2 * r + 1];
    }

    // 4) Multiply and stream the stores out (evict-first: keep the param
    //    table resident in L2).
#pragma unroll
    for (int k = 0; k < UNROLL; k++) {
        const int r = tid + k * stride;
        float4 o0, o1;
        o0.x = p[k] * x0[k].x; o0.y = p[k] * x0[k].y;
        o0.z = p[k] * x0[k].z; o0.w = p[k] * x0[k].w;
        o1.x = p[k] * x1[k].x; o1.y = p[k] * x1[k].y;
        o1.z = p[k] * x1[k].z; o1.w = p[k] * x1[k].w;
        __stcs(&out[2 * r],     o0);
        __stcs(&out[2 * r + 1], o1);
    }
}

extern "C" void kernel_launch(void* const* d_in, const int* in_sizes, int n_in,
                              void* d_out, int out_size)
{
    const float4* xs     = (const float4*)d_in[0];
    const int*    idx    = (const int*)d_in[1];
    const float*  params = (const float*)d_in[2];
    float4*       out    = (float4*)d_out;

    gather_mul_kernel<<<BLOCKS, THREADS>>>(xs, idx, params, out);
}

// round 4
// speedup vs baseline: 1.2720x; 1.2226x over previous
#include <cuda_runtime.h>
#include <stdint.h>

// out[i, 0:8] = params[idx[i]] * xs[i, 0:8]
// xs: float32 [N, 8]; idx: int32 [N]; params: float32 [V]; out: float32 [N, 8]
// N = 4194304, V = 1048576.
//
// Layout: 2 threads per row, one float4 half-row each -> 16B lane-contiguous
// streaming accesses (fully dense wavefronts). Lane pairs share the idx/param
// address (broadcast). Streaming accesses use evict-first hints so the 4 MB
// param table stays L2-resident.

#define N_ROWS  4194304
#define ITEMS   (2 * N_ROWS)            // 8M float4 half-rows
#define UNROLL  4
#define THREADS 256
#define BLOCKS  (ITEMS / (UNROLL * THREADS))   // 8192

__global__ __launch_bounds__(THREADS) void gather_mul_kernel(
    const float4* __restrict__ xs,     // [ITEMS]
    const int*    __restrict__ idx,    // [N] int32
    const float*  __restrict__ params, // [V]
    float4*       __restrict__ out)    // [ITEMS]
{
    const int t = blockIdx.x * THREADS + threadIdx.x;
    const int S = BLOCKS * THREADS;    // 2M items per sweep

    // 1) Batch index loads (lane pairs share an address -> broadcast).
    int j[UNROLL];
#pragma unroll
    for (int k = 0; k < UNROLL; k++)
        j[k] = __ldcs(idx + ((t + k * S) >> 1));

    // 2) Batch param gathers (keep default caching: table stays in L2/L1).
    float p[UNROLL];
#pragma unroll
    for (int k = 0; k < UNROLL; k++)
        p[k] = __ldg(params + j[k]);

    // 3) Batch xs half-row loads: 16B lane-contiguous, evict-first.
    float4 x[UNROLL];
#pragma unroll
    for (int k = 0; k < UNROLL; k++)
        x[k] = __ldcs(xs + t + k * S);

    // 4) Multiply + streaming stores (evict-first).
#pragma unroll
    for (int k = 0; k < UNROLL; k++) {
        float4 o;
        o.x = p[k] * x[k].x;
        o.y = p[k] * x[k].y;
        o.z = p[k] * x[k].z;
        o.w = p[k] * x[k].w;
        __stcs(out + t + k * S, o);
    }
}

extern "C" void kernel_launch(void* const* d_in, const int* in_sizes, int n_in,
                              void* d_out, int out_size)
{
    const float4* xs     = (const float4*)d_in[0];
    const int*    idx    = (const int*)d_in[1];
    const float*  params = (const float*)d_in[2];
    float4*       out    = (float4*)d_out;

    gather_mul_kernel<<<BLOCKS, THREADS>>>(xs, idx, params, out);
}